// round 14
// baseline (speedup 1.0000x reference)
#include <cuda_runtime.h>
#include <cstdint>

#define BATCH   16
#define NANCH   25200
#define NCH     85
#define NCLS    80
#define TOPK    1024
#define MAXDET  300
#define CONF_THR 0.6f
#define IOU_THR  0.45f
#define OFFS     4096.0f
#define NBINS    4096
#define APB      256          // anchors per block in k_score

// ---------------- static device scratch (no allocations allowed) ----------------
__device__ float         g_score[BATCH * NANCH];
__device__ unsigned char g_cls[BATCH * NANCH];
__device__ int           g_topk_idx[BATCH * TOPK];
__device__ float         g_topk_score[BATCH * TOPK];
__device__ float         g_clsf[BATCH * TOPK];
__device__ float4        g_obox[BATCH * TOPK];
__device__ float4        g_nmsbox[BATCH * TOPK];
__device__ __align__(16) unsigned int g_mask[BATCH * TOPK * 32];

// ---------------- K1: smem-tiled score / class (512 threads, strided compute) ---
__global__ void k_score(const float* __restrict__ pred) {
    __shared__ float sp[APB * NCH];            // 87040 B
    int b  = blockIdx.y;
    int a0 = blockIdx.x * APB;
    int tid = threadIdx.x;                     // 512 threads
    int cnt = min(APB, NANCH - a0);            // 256 or 112; both %4==0
    int n4  = (cnt * NCH) >> 2;                // float4 count (divisible)

    const float4* src = (const float4*)(pred + ((size_t)b * NANCH + a0) * NCH);
    float4* dst = (float4*)sp;
    for (int i = tid; i < n4; i += 512) dst[i] = src[i];
    __syncthreads();

    for (int a = tid; a < cnt; a += 512) {
        const float* row = sp + a * NCH;
        float obj = row[4];
        float best = -2.0f; int bidx = 0;
        #pragma unroll
        for (int j = 0; j < NCLS; j++) {
            float p = __fmul_rn(obj, row[5 + j]);
            if (p > best) { best = p; bidx = j; }   // strict > = first max (jnp.argmax)
        }
        bool valid = (obj > CONF_THR) && (best > CONF_THR);
        int ga = b * NANCH + a0 + a;
        g_score[ga] = valid ? best : -1.0f;
        g_cls[ga]   = (unsigned char)bidx;
    }
}

// ---- warp-local bitonic stages (j = j0 .. 1) on 2 register keys per lane -------
__device__ __forceinline__ void wl_stages(unsigned long long& a, unsigned long long& b,
                                          int e0, int k, int j0) {
    for (int j = j0; j >= 2; j >>= 1) {
        int jl = j >> 1;
        unsigned long long oa = __shfl_xor_sync(0xffffffffu, a, jl);
        unsigned long long ob = __shfl_xor_sync(0xffffffffu, b, jl);
        bool asc   = ((e0 & k) == 0);
        bool lower = ((e0 & j) == 0);
        bool keepmin = (lower == asc);
        a = keepmin ? (a < oa ? a : oa) : (a > oa ? a : oa);
        b = keepmin ? (b < ob ? b : ob) : (b > ob ? b : ob);
    }
    bool asc = ((e0 & k) == 0);
    if ((a > b) == asc) { unsigned long long t = a; a = b; b = t; }
}

// ---------------- K2: per-image exact top-1024 via histogram + hybrid bitonic ---
__global__ void k_select(const float* __restrict__ pred) {
    int b   = blockIdx.x;
    int tid = threadIdx.x;                 // 1024 threads
    __shared__ int hist[NBINS];
    __shared__ unsigned long long sbuf[2 * TOPK];
    __shared__ int partial[1024];
    __shared__ int sup[32];
    __shared__ int sh_T;
    __shared__ int counter;

    for (int i = tid; i < NBINS; i += 1024) hist[i] = 0;
    if (tid == 0) counter = 0;
    __syncthreads();

    const float4* sc4 = (const float4*)(g_score + (size_t)b * NANCH);
    const int N4 = NANCH / 4;              // 6300, exact
    const float kBinScale = (float)NBINS / 0.4f;

    for (int i = tid; i < N4; i += 1024) {
        float4 v = sc4[i];
        float s0 = v.x, s1 = v.y, s2 = v.z, s3 = v.w;
        if (s0 > CONF_THR) { int bin = min(max((int)((s0 - CONF_THR) * kBinScale), 0), NBINS - 1); atomicAdd(&hist[bin], 1); }
        if (s1 > CONF_THR) { int bin = min(max((int)((s1 - CONF_THR) * kBinScale), 0), NBINS - 1); atomicAdd(&hist[bin], 1); }
        if (s2 > CONF_THR) { int bin = min(max((int)((s2 - CONF_THR) * kBinScale), 0), NBINS - 1); atomicAdd(&hist[bin], 1); }
        if (s3 > CONF_THR) { int bin = min(max((int)((s3 - CONF_THR) * kBinScale), 0), NBINS - 1); atomicAdd(&hist[bin], 1); }
    }
    __syncthreads();

    int ps = 0;
    #pragma unroll
    for (int k = 0; k < 4; k++) ps += hist[4 * tid + k];
    partial[tid] = ps;
    __syncthreads();

    if (tid < 32) {
        int s = 0;
        for (int g = 0; g < 32; g++) s += partial[32 * tid + g];
        sup[tid] = s;
        __syncwarp();
        if (tid == 0) {
            int acc = 0, T = 0, l;
            for (l = 31; l >= 0; l--) { if (acc + sup[l] >= TOPK) break; acc += sup[l]; }
            if (l >= 0) {
                int g;
                for (g = 31; g >= 0; g--) { int v = partial[32 * l + g]; if (acc + v >= TOPK) break; acc += v; }
                if (g < 0) g = 0;
                int bb;
                for (bb = 3; bb >= 0; bb--) { int v = hist[4 * (32 * l + g) + bb]; if (acc + v >= TOPK) break; acc += v; }
                if (bb < 0) bb = 0;
                T = 4 * (32 * l + g) + bb;
            }
            sh_T = T;
        }
    }
    __syncthreads();
    int T = sh_T;

    for (int i = tid; i < N4; i += 1024) {
        float4 v = sc4[i];
        #pragma unroll
        for (int u = 0; u < 4; u++) {
            float s = (u == 0) ? v.x : (u == 1) ? v.y : (u == 2) ? v.z : v.w;
            if (s > CONF_THR) {
                int bin = min(max((int)((s - CONF_THR) * kBinScale), 0), NBINS - 1);
                if (bin >= T) {
                    int pos = atomicAdd(&counter, 1);
                    if (pos < 2 * TOPK) {
                        unsigned int ub = __float_as_uint(s) ^ 0x80000000u;  // order-preserving
                        sbuf[pos] = (((unsigned long long)(~ub)) << 32) | (unsigned int)(4 * i + u);
                    }
                }
            }
        }
    }
    __syncthreads();
    int M = min(counter, 2 * TOPK);
    for (int i = tid; i < 2 * TOPK; i += 1024)
        if (i >= M) sbuf[i] = 0xFFFFFFFFFFFFFFFFull;
    __syncthreads();

    // hybrid bitonic sort ascending over 2048 keys:
    //   primary ~score_bits (=> score descending), ties idx ascending
    {
        int lane = tid & 31, wchunk = tid >> 5;
        int e0 = wchunk * 64 + 2 * lane;           // this lane's even element

        unsigned long long a = sbuf[e0], bk = sbuf[e0 + 1];
        #pragma unroll
        for (int k = 2; k <= 64; k <<= 1)
            wl_stages(a, bk, e0, k, (k >> 1) > 32 ? 32 : (k >> 1));
        sbuf[e0] = a; sbuf[e0 + 1] = bk;
        __syncthreads();

        for (int k = 128; k <= 2048; k <<= 1) {
            for (int j = k >> 1; j >= 64; j >>= 1) {
                #pragma unroll
                for (int e = tid; e < 2 * TOPK; e += 1024) {
                    int partner = e ^ j;
                    if (partner > e) {
                        bool asc = ((e & k) == 0);
                        unsigned long long x = sbuf[e], y = sbuf[partner];
                        if ((x > y) == asc) { sbuf[e] = y; sbuf[partner] = x; }
                    }
                }
                __syncthreads();
            }
            a = sbuf[e0]; bk = sbuf[e0 + 1];
            wl_stages(a, bk, e0, k, 32);
            sbuf[e0] = a; sbuf[e0 + 1] = bk;
            __syncthreads();
        }
    }

    // emit top-1024: idx, score, class, unoffset box, class-offset nms box
    if (tid < TOPK) {
        int slot = b * TOPK + tid;
        if (tid < M) {
            unsigned long long key = sbuf[tid];
            int idx = (int)(key & 0xFFFFFFFFu);
            unsigned int u = ~((unsigned int)(key >> 32));
            float s = __uint_as_float(u ^ 0x80000000u);
            g_topk_score[slot] = s;
            g_topk_idx[slot]   = idx;
            const float* p = pred + ((size_t)b * NANCH + idx) * NCH;
            float cx = p[0], cy = p[1], w = p[2], h = p[3];
            float hw = __fmul_rn(w, 0.5f), hh = __fmul_rn(h, 0.5f);
            float x1 = __fsub_rn(cx, hw), y1 = __fsub_rn(cy, hh);
            float x2 = __fadd_rn(cx, hw), y2 = __fadd_rn(cy, hh);
            float clsf = (float)g_cls[(size_t)b * NANCH + idx];
            float off = __fmul_rn(clsf, OFFS);
            g_obox[slot] = make_float4(x1, y1, x2, y2);
            g_clsf[slot] = clsf;
            g_nmsbox[slot] = make_float4(__fadd_rn(x1, off), __fadd_rn(y1, off),
                                         __fadd_rn(x2, off), __fadd_rn(y2, off));
        } else {
            g_topk_score[slot] = -1.0f;
            g_topk_idx[slot]   = 0;
            g_obox[slot] = make_float4(0.f, 0.f, 0.f, 0.f);
            g_clsf[slot] = 0.f;
            float far = -1.0e9f - (float)tid * 16.0f;   // inert: never kept, never suppresses
            g_nmsbox[slot] = make_float4(far, far, far + 1.0f, far + 1.0f);
        }
    }
}

// ---------------- K3: triangular suppression bitmask ---------------------------
__device__ __forceinline__ unsigned int iou_bit(const float4& bi, float area_i,
                                                const float4& bj, float area_j) {
    float ltx = fmaxf(bi.x, bj.x), lty = fmaxf(bi.y, bj.y);
    float rbx = fminf(bi.z, bj.z), rby = fminf(bi.w, bj.w);
    float wx = fmaxf(__fsub_rn(rbx, ltx), 0.0f);
    float wy = fmaxf(__fsub_rn(rby, lty), 0.0f);
    float inter = __fmul_rn(wx, wy);
    if (inter > 0.0f) {                     // inter==0 -> iou==+0, never > 0.45
        float denom = __fadd_rn(__fsub_rn(__fadd_rn(area_i, area_j), inter), 1e-9f);
        float iou = inter / denom;
        if (iou > IOU_THR) return 1u;
    }
    return 0u;
}

__global__ void k_mask() {
    int b = blockIdx.x, q = blockIdx.y;     // q in [0,8): column eighth (128 cols)
    int i = threadIdx.x;                    // 1024 threads, one row each
    __shared__ float4 boxes[TOPK];
    __shared__ float  areas[TOPK];
    for (int t = threadIdx.x; t < TOPK; t += 1024) {
        float4 v = g_nmsbox[b * TOPK + t];
        boxes[t] = v;
        areas[t] = __fmul_rn(__fsub_rn(v.z, v.x), __fsub_rn(v.w, v.y));
    }
    __syncthreads();

    float4 bi = boxes[i];
    float area_i = areas[i];
    int j0 = q * 128;
    unsigned int* mrow = &g_mask[((size_t)b * TOPK + i) * 32 + q * 4];
    #pragma unroll
    for (int w = 0; w < 4; w++) {
        int jbase = j0 + w * 32;
        unsigned int m = 0;
        if (jbase > i) {
            // whole word strictly above the diagonal: no j>i test needed
            #pragma unroll 8
            for (int t = 0; t < 32; t++) {
                int j = jbase + t;
                m |= iou_bit(bi, area_i, boxes[j], areas[j]) << t;
            }
        } else if (jbase + 31 > i) {
            // straddling word: test each element
            #pragma unroll 8
            for (int t = 0; t < 32; t++) {
                int j = jbase + t;
                if (j > i)
                    m |= iou_bit(bi, area_i, boxes[j], areas[j]) << t;
            }
        }
        // else: word entirely at/below diagonal -> all zero
        mrow[w] = m;
    }
}

// ---------------- K4: full-mask smem + REDUX.MIN warp walk ----------------------
__global__ void k_out(const float* __restrict__ logits,
                      float* __restrict__ out) {
    extern __shared__ unsigned char dyn[];
    unsigned int* s_mask32 = (unsigned int*)dyn;                    // TOPK*32 u32 = 128 KB
    float* s_score = (float*)(dyn + TOPK * 32 * sizeof(unsigned int)); // 4 KB
    __shared__ int sel[MAXDET];
    __shared__ int sh_count;

    int b   = blockIdx.x;
    int tid = threadIdx.x;                  // 1024 threads

    float myscore = g_topk_score[b * TOPK + tid];
    s_score[tid] = myscore;

    // stage entire mask: 8192 uint4 -> 8 per thread, coalesced
    const uint4* gm = (const uint4*)(g_mask + (size_t)b * TOPK * 32);
    uint4* sm4 = (uint4*)s_mask32;
    #pragma unroll
    for (int t = 0; t < 8; t++) sm4[t * 1024 + tid] = gm[t * 1024 + tid];

    // validity is a prefix (scores sorted desc): nv = number of valid entries
    int nv = __syncthreads_count(myscore > CONF_THR);

    if (tid < 32) {
        // lane L owns removed bits for indices [32L, 32L+32)
        int lane = tid;
        int r = nv - lane * 32;
        unsigned int validw = (r >= 32) ? 0xFFFFFFFFu : ((r <= 0) ? 0u : ((1u << r) - 1u));
        unsigned int rem = 0;
        int count = 0;
        while (count < MAXDET) {
            unsigned int todo = validw & ~rem;
            unsigned int cand = todo ? ((unsigned int)(lane * 32) + __ffs(todo) - 1u)
                                     : 0xFFFFFFFFu;
            unsigned int i = __reduce_min_sync(0xffffffffu, cand);
            if (i == 0xFFFFFFFFu) break;
            if (lane == 0) sel[count] = (int)i;
            count++;
            rem |= s_mask32[(size_t)i * 32 + lane];        // parallel OR, one LDS per lane
            if ((i >> 5) == (unsigned int)lane) rem |= (1u << (i & 31u));  // consume kept bit
        }
        if (lane == 0) sh_count = count;
    }
    __syncthreads();
    int count = sh_count;

    float* det  = out;                                      // [B,300,6]
    float* vout = out + BATCH * MAXDET * 6;                 // [B,300]
    float* lout = vout + BATCH * MAXDET;                    // [B,300,80]

    for (int s = tid; s < MAXDET; s += 1024) {
        float d0 = 0, d1 = 0, d2 = 0, d3 = 0, d4 = 0, d5 = 0, v = 0;
        if (s < count) {
            int i = sel[s];
            float4 o = g_obox[b * TOPK + i];                // linear per-slot arrays only
            d0 = o.x; d1 = o.y; d2 = o.z; d3 = o.w;
            d4 = s_score[i];
            d5 = g_clsf[b * TOPK + i];
            v = 1.0f;
        }
        float* dr = det + ((size_t)b * MAXDET + s) * 6;
        dr[0] = d0; dr[1] = d1; dr[2] = d2; dr[3] = d3; dr[4] = d4; dr[5] = d5;
        vout[b * MAXDET + s] = v;
    }

    for (int e = tid; e < MAXDET * NCLS; e += 1024) {
        int s = e / NCLS, c = e % NCLS;
        float v = 0.0f;
        if (s < count) {
            int i   = sel[s];
            int idx = g_topk_idx[b * TOPK + i];
            v = logits[((size_t)b * NANCH + idx) * NCLS + c];
        }
        lout[((size_t)b * MAXDET + s) * NCLS + c] = v;
    }
}

// ---------------- launch --------------------------------------------------------
extern "C" void kernel_launch(void* const* d_in, const int* in_sizes, int n_in,
                              void* d_out, int out_size) {
    (void)in_sizes; (void)n_in; (void)out_size;
    const float* pred   = (const float*)d_in[0];
    const float* logits = (const float*)d_in[1];
    float* out = (float*)d_out;

    const int KOUT_SMEM = TOPK * 32 * (int)sizeof(unsigned int) + TOPK * (int)sizeof(float);
    cudaFuncSetAttribute(k_out, cudaFuncAttributeMaxDynamicSharedMemorySize, KOUT_SMEM);

    int nxblocks = (NANCH + APB - 1) / APB;          // 99
    k_score<<<dim3(nxblocks, BATCH), 512>>>(pred);
    k_select<<<BATCH, 1024>>>(pred);
    k_mask<<<dim3(BATCH, 8), 1024>>>();
    k_out<<<BATCH, 1024, KOUT_SMEM>>>(logits, out);
}

// round 15
// speedup vs baseline: 1.4383x; 1.4383x over previous
#include <cuda_runtime.h>
#include <cstdint>

#define BATCH   16
#define NANCH   25200
#define NCH     85
#define NCLS    80
#define TOPK    1024
#define MAXDET  300
#define CONF_THR 0.6f
#define IOU_THR  0.45f
#define OFFS     4096.0f
#define NBINS    4096
#define APB      256          // anchors per block in k_score

// ---------------- static device scratch (no allocations allowed) ----------------
__device__ float         g_score[BATCH * NANCH];
__device__ unsigned char g_cls[BATCH * NANCH];
__device__ int           g_topk_idx[BATCH * TOPK];
__device__ float         g_topk_score[BATCH * TOPK];
__device__ float         g_clsf[BATCH * TOPK];
__device__ float4        g_obox[BATCH * TOPK];
__device__ float4        g_nmsbox[BATCH * TOPK];
__device__ __align__(16) unsigned int g_mask[BATCH * TOPK * 32];

// ---------------- K1: smem-tiled score / class (512 threads, strided compute) ---
__global__ void k_score(const float* __restrict__ pred) {
    __shared__ float sp[APB * NCH];            // 87040 B
    int b  = blockIdx.y;
    int a0 = blockIdx.x * APB;
    int tid = threadIdx.x;                     // 512 threads
    int cnt = min(APB, NANCH - a0);            // 256 or 112; both %4==0
    int n4  = (cnt * NCH) >> 2;                // float4 count (divisible)

    const float4* src = (const float4*)(pred + ((size_t)b * NANCH + a0) * NCH);
    float4* dst = (float4*)sp;
    for (int i = tid; i < n4; i += 512) dst[i] = src[i];
    __syncthreads();

    for (int a = tid; a < cnt; a += 512) {
        const float* row = sp + a * NCH;
        float obj = row[4];
        float best = -2.0f; int bidx = 0;
        #pragma unroll
        for (int j = 0; j < NCLS; j++) {
            float p = __fmul_rn(obj, row[5 + j]);
            if (p > best) { best = p; bidx = j; }   // strict > = first max (jnp.argmax)
        }
        bool valid = (obj > CONF_THR) && (best > CONF_THR);
        int ga = b * NANCH + a0 + a;
        g_score[ga] = valid ? best : -1.0f;
        g_cls[ga]   = (unsigned char)bidx;
    }
}

// ---- warp-local bitonic stages (j = j0 .. 1) on 2 register keys per lane -------
__device__ __forceinline__ void wl_stages(unsigned long long& a, unsigned long long& b,
                                          int e0, int k, int j0) {
    for (int j = j0; j >= 2; j >>= 1) {
        int jl = j >> 1;
        unsigned long long oa = __shfl_xor_sync(0xffffffffu, a, jl);
        unsigned long long ob = __shfl_xor_sync(0xffffffffu, b, jl);
        bool asc   = ((e0 & k) == 0);
        bool lower = ((e0 & j) == 0);
        bool keepmin = (lower == asc);
        a = keepmin ? (a < oa ? a : oa) : (a > oa ? a : oa);
        b = keepmin ? (b < ob ? b : ob) : (b > ob ? b : ob);
    }
    bool asc = ((e0 & k) == 0);
    if ((a > b) == asc) { unsigned long long t = a; a = b; b = t; }
}

// ---------------- K2: per-image exact top-1024 via histogram + partial bitonic --
__global__ void k_select(const float* __restrict__ pred) {
    int b   = blockIdx.x;
    int tid = threadIdx.x;                 // 1024 threads
    __shared__ int hist[NBINS];
    __shared__ unsigned long long sbuf[2 * TOPK];
    __shared__ int partial[1024];
    __shared__ int sup[32];
    __shared__ int sh_T;
    __shared__ int counter;

    for (int i = tid; i < NBINS; i += 1024) hist[i] = 0;
    if (tid == 0) counter = 0;
    __syncthreads();

    const float4* sc4 = (const float4*)(g_score + (size_t)b * NANCH);
    const int N4 = NANCH / 4;              // 6300, exact
    const float kBinScale = (float)NBINS / 0.4f;

    for (int i = tid; i < N4; i += 1024) {
        float4 v = sc4[i];
        float s0 = v.x, s1 = v.y, s2 = v.z, s3 = v.w;
        if (s0 > CONF_THR) { int bin = min(max((int)((s0 - CONF_THR) * kBinScale), 0), NBINS - 1); atomicAdd(&hist[bin], 1); }
        if (s1 > CONF_THR) { int bin = min(max((int)((s1 - CONF_THR) * kBinScale), 0), NBINS - 1); atomicAdd(&hist[bin], 1); }
        if (s2 > CONF_THR) { int bin = min(max((int)((s2 - CONF_THR) * kBinScale), 0), NBINS - 1); atomicAdd(&hist[bin], 1); }
        if (s3 > CONF_THR) { int bin = min(max((int)((s3 - CONF_THR) * kBinScale), 0), NBINS - 1); atomicAdd(&hist[bin], 1); }
    }
    __syncthreads();

    int ps = 0;
    #pragma unroll
    for (int k = 0; k < 4; k++) ps += hist[4 * tid + k];
    partial[tid] = ps;
    __syncthreads();

    if (tid < 32) {
        int s = 0;
        for (int g = 0; g < 32; g++) s += partial[32 * tid + g];
        sup[tid] = s;
        __syncwarp();
        if (tid == 0) {
            int acc = 0, T = 0, l;
            for (l = 31; l >= 0; l--) { if (acc + sup[l] >= TOPK) break; acc += sup[l]; }
            if (l >= 0) {
                int g;
                for (g = 31; g >= 0; g--) { int v = partial[32 * l + g]; if (acc + v >= TOPK) break; acc += v; }
                if (g < 0) g = 0;
                int bb;
                for (bb = 3; bb >= 0; bb--) { int v = hist[4 * (32 * l + g) + bb]; if (acc + v >= TOPK) break; acc += v; }
                if (bb < 0) bb = 0;
                T = 4 * (32 * l + g) + bb;
            }
            sh_T = T;
        }
    }
    __syncthreads();
    int T = sh_T;

    for (int i = tid; i < N4; i += 1024) {
        float4 v = sc4[i];
        #pragma unroll
        for (int u = 0; u < 4; u++) {
            float s = (u == 0) ? v.x : (u == 1) ? v.y : (u == 2) ? v.z : v.w;
            if (s > CONF_THR) {
                int bin = min(max((int)((s - CONF_THR) * kBinScale), 0), NBINS - 1);
                if (bin >= T) {
                    int pos = atomicAdd(&counter, 1);
                    if (pos < 2 * TOPK) {
                        unsigned int ub = __float_as_uint(s) ^ 0x80000000u;  // order-preserving
                        sbuf[pos] = (((unsigned long long)(~ub)) << 32) | (unsigned int)(4 * i + u);
                    }
                }
            }
        }
    }
    __syncthreads();
    int M = min(counter, 2 * TOPK);
    for (int i = tid; i < 2 * TOPK; i += 1024)
        if (i >= M) sbuf[i] = 0xFFFFFFFFFFFFFFFFull;
    __syncthreads();

    // partial bitonic: full network through k=1024, then min-merge + sort of the
    // lower 1024 only (upper half never emitted). Identical compare-network prefix.
    {
        int lane = tid & 31, wchunk = tid >> 5;
        int e0 = wchunk * 64 + 2 * lane;           // this lane's even element

        unsigned long long a = sbuf[e0], bk = sbuf[e0 + 1];
        #pragma unroll
        for (int k = 2; k <= 64; k <<= 1)
            wl_stages(a, bk, e0, k, (k >> 1) > 32 ? 32 : (k >> 1));
        sbuf[e0] = a; sbuf[e0 + 1] = bk;
        __syncthreads();

        for (int k = 128; k <= 1024; k <<= 1) {
            for (int j = k >> 1; j >= 64; j >>= 1) {
                #pragma unroll
                for (int e = tid; e < 2 * TOPK; e += 1024) {
                    int partner = e ^ j;
                    if (partner > e) {
                        bool asc = ((e & k) == 0);
                        unsigned long long x = sbuf[e], y = sbuf[partner];
                        if ((x > y) == asc) { sbuf[e] = y; sbuf[partner] = x; }
                    }
                }
                __syncthreads();
            }
            a = sbuf[e0]; bk = sbuf[e0 + 1];
            wl_stages(a, bk, e0, k, 32);
            sbuf[e0] = a; sbuf[e0 + 1] = bk;
            __syncthreads();
        }

        // k=2048 stage, ascending everywhere (e&2048==0 for e<2048):
        // j=1024 min-merge -> lower half holds the 1024 smallest (bitonic)
        {
            unsigned long long x = sbuf[tid], y = sbuf[tid + TOPK];
            if (x > y) { sbuf[tid] = y; sbuf[tid + TOPK] = x; }
        }
        __syncthreads();
        // finish lower half only: smem steps j=512..64, all ascending
        for (int j = 512; j >= 64; j >>= 1) {
            int partner = tid ^ j;
            if (partner > tid) {
                unsigned long long x = sbuf[tid], y = sbuf[partner];
                if (x > y) { sbuf[tid] = y; sbuf[partner] = x; }
            }
            __syncthreads();
        }
        // warp-local j=32..1 on lower-half chunks (asc: k bit above range)
        if (wchunk < 16) {
            a = sbuf[e0]; bk = sbuf[e0 + 1];
            wl_stages(a, bk, e0, 4096, 32);
            sbuf[e0] = a; sbuf[e0 + 1] = bk;
        }
        __syncthreads();
    }

    // emit top-1024: idx, score, class, unoffset box, class-offset nms box
    if (tid < TOPK) {
        int slot = b * TOPK + tid;
        if (tid < M) {
            unsigned long long key = sbuf[tid];
            int idx = (int)(key & 0xFFFFFFFFu);
            unsigned int u = ~((unsigned int)(key >> 32));
            float s = __uint_as_float(u ^ 0x80000000u);
            g_topk_score[slot] = s;
            g_topk_idx[slot]   = idx;
            const float* p = pred + ((size_t)b * NANCH + idx) * NCH;
            float cx = p[0], cy = p[1], w = p[2], h = p[3];
            float hw = __fmul_rn(w, 0.5f), hh = __fmul_rn(h, 0.5f);
            float x1 = __fsub_rn(cx, hw), y1 = __fsub_rn(cy, hh);
            float x2 = __fadd_rn(cx, hw), y2 = __fadd_rn(cy, hh);
            float clsf = (float)g_cls[(size_t)b * NANCH + idx];
            float off = __fmul_rn(clsf, OFFS);
            g_obox[slot] = make_float4(x1, y1, x2, y2);
            g_clsf[slot] = clsf;
            g_nmsbox[slot] = make_float4(__fadd_rn(x1, off), __fadd_rn(y1, off),
                                         __fadd_rn(x2, off), __fadd_rn(y2, off));
        } else {
            g_topk_score[slot] = -1.0f;
            g_topk_idx[slot]   = 0;
            g_obox[slot] = make_float4(0.f, 0.f, 0.f, 0.f);
            g_clsf[slot] = 0.f;
            float far = -1.0e9f - (float)tid * 16.0f;   // inert: never kept, never suppresses
            g_nmsbox[slot] = make_float4(far, far, far + 1.0f, far + 1.0f);
        }
    }
}

// ---------------- K3: suppression bitmask; div only when inter > 0 -------------
__global__ void k_mask() {
    int b = blockIdx.x, q = blockIdx.y;     // q in [0,8): column eighth (128 cols)
    int i = threadIdx.x;                    // 1024 threads, one row each
    __shared__ float4 boxes[TOPK];
    __shared__ float  areas[TOPK];
    for (int t = threadIdx.x; t < TOPK; t += 1024) {
        float4 v = g_nmsbox[b * TOPK + t];
        boxes[t] = v;
        areas[t] = __fmul_rn(__fsub_rn(v.z, v.x), __fsub_rn(v.w, v.y));
    }
    __syncthreads();

    float4 bi = boxes[i];
    float area_i = areas[i];
    int j0 = q * 128;
    #pragma unroll
    for (int w = 0; w < 4; w++) {
        unsigned int m = 0;
        #pragma unroll 4
        for (int t = 0; t < 32; t++) {
            int j = j0 + w * 32 + t;
            if (j > i) {
                float4 bj = boxes[j];
                float ltx = fmaxf(bi.x, bj.x), lty = fmaxf(bi.y, bj.y);
                float rbx = fminf(bi.z, bj.z), rby = fminf(bi.w, bj.w);
                float wx = fmaxf(__fsub_rn(rbx, ltx), 0.0f);
                float wy = fmaxf(__fsub_rn(rby, lty), 0.0f);
                float inter = __fmul_rn(wx, wy);
                if (inter > 0.0f) {         // inter==0 -> iou==+0, never > 0.45
                    float denom = __fadd_rn(__fsub_rn(__fadd_rn(area_i, areas[j]), inter), 1e-9f);
                    float iou = inter / denom;
                    if (iou > IOU_THR) m |= (1u << t);
                }
            }
        }
        g_mask[((size_t)b * TOPK + i) * 32 + q * 4 + w] = m;
    }
}

// ---------------- K4: full-mask smem + REDUX.MIN warp walk ----------------------
__global__ void k_out(const float* __restrict__ logits,
                      float* __restrict__ out) {
    extern __shared__ unsigned char dyn[];
    unsigned int* s_mask32 = (unsigned int*)dyn;                    // TOPK*32 u32 = 128 KB
    float* s_score = (float*)(dyn + TOPK * 32 * sizeof(unsigned int)); // 4 KB
    __shared__ int sel[MAXDET];
    __shared__ int sh_count;

    int b   = blockIdx.x;
    int tid = threadIdx.x;                  // 1024 threads

    float myscore = g_topk_score[b * TOPK + tid];
    s_score[tid] = myscore;

    // stage entire mask: 8192 uint4 -> 8 per thread, coalesced
    const uint4* gm = (const uint4*)(g_mask + (size_t)b * TOPK * 32);
    uint4* sm4 = (uint4*)s_mask32;
    #pragma unroll
    for (int t = 0; t < 8; t++) sm4[t * 1024 + tid] = gm[t * 1024 + tid];

    // validity is a prefix (scores sorted desc): nv = number of valid entries
    int nv = __syncthreads_count(myscore > CONF_THR);

    if (tid < 32) {
        // lane L owns removed bits for indices [32L, 32L+32)
        int lane = tid;
        int r = nv - lane * 32;
        unsigned int validw = (r >= 32) ? 0xFFFFFFFFu : ((r <= 0) ? 0u : ((1u << r) - 1u));
        unsigned int rem = 0;
        int count = 0;
        while (count < MAXDET) {
            unsigned int todo = validw & ~rem;
            unsigned int cand = todo ? ((unsigned int)(lane * 32) + __ffs(todo) - 1u)
                                     : 0xFFFFFFFFu;
            unsigned int i = __reduce_min_sync(0xffffffffu, cand);
            if (i == 0xFFFFFFFFu) break;
            if (lane == 0) sel[count] = (int)i;
            count++;
            rem |= s_mask32[(size_t)i * 32 + lane];        // parallel OR, one LDS per lane
            if ((i >> 5) == (unsigned int)lane) rem |= (1u << (i & 31u));  // consume kept bit
        }
        if (lane == 0) sh_count = count;
    }
    __syncthreads();
    int count = sh_count;

    float* det  = out;                                      // [B,300,6]
    float* vout = out + BATCH * MAXDET * 6;                 // [B,300]
    float* lout = vout + BATCH * MAXDET;                    // [B,300,80]

    for (int s = tid; s < MAXDET; s += 1024) {
        float d0 = 0, d1 = 0, d2 = 0, d3 = 0, d4 = 0, d5 = 0, v = 0;
        if (s < count) {
            int i = sel[s];
            float4 o = g_obox[b * TOPK + i];                // linear per-slot arrays only
            d0 = o.x; d1 = o.y; d2 = o.z; d3 = o.w;
            d4 = s_score[i];
            d5 = g_clsf[b * TOPK + i];
            v = 1.0f;
        }
        float* dr = det + ((size_t)b * MAXDET + s) * 6;
        dr[0] = d0; dr[1] = d1; dr[2] = d2; dr[3] = d3; dr[4] = d4; dr[5] = d5;
        vout[b * MAXDET + s] = v;
    }

    for (int e = tid; e < MAXDET * NCLS; e += 1024) {
        int s = e / NCLS, c = e % NCLS;
        float v = 0.0f;
        if (s < count) {
            int i   = sel[s];
            int idx = g_topk_idx[b * TOPK + i];
            v = logits[((size_t)b * NANCH + idx) * NCLS + c];
        }
        lout[((size_t)b * MAXDET + s) * NCLS + c] = v;
    }
}

// ---------------- launch --------------------------------------------------------
extern "C" void kernel_launch(void* const* d_in, const int* in_sizes, int n_in,
                              void* d_out, int out_size) {
    (void)in_sizes; (void)n_in; (void)out_size;
    const float* pred   = (const float*)d_in[0];
    const float* logits = (const float*)d_in[1];
    float* out = (float*)d_out;

    const int KOUT_SMEM = TOPK * 32 * (int)sizeof(unsigned int) + TOPK * (int)sizeof(float);
    cudaFuncSetAttribute(k_out, cudaFuncAttributeMaxDynamicSharedMemorySize, KOUT_SMEM);

    int nxblocks = (NANCH + APB - 1) / APB;          // 99
    k_score<<<dim3(nxblocks, BATCH), 512>>>(pred);
    k_select<<<BATCH, 1024>>>(pred);
    k_mask<<<dim3(BATCH, 8), 1024>>>();
    k_out<<<BATCH, 1024, KOUT_SMEM>>>(logits, out);
}

// round 16
// speedup vs baseline: 1.4529x; 1.0102x over previous
#include <cuda_runtime.h>
#include <cstdint>

#define BATCH   16
#define NANCH   25200
#define NCH     85
#define NCLS    80
#define TOPK    1024
#define MAXDET  300
#define CONF_THR 0.6f
#define IOU_THR  0.45f
#define OFFS     4096.0f
#define NBINS    4096
#define APB      256          // anchors per block in k_score

// ---------------- static device scratch (no allocations allowed) ----------------
__device__ float         g_score[BATCH * NANCH];
__device__ unsigned char g_cls[BATCH * NANCH];
__device__ int           g_topk_idx[BATCH * TOPK];
__device__ float         g_topk_score[BATCH * TOPK];
__device__ float         g_clsf[BATCH * TOPK];
__device__ float4        g_obox[BATCH * TOPK];
__device__ float4        g_nmsbox[BATCH * TOPK];
__device__ __align__(16) unsigned int g_mask[BATCH * TOPK * 32];

// ---------------- K1: smem-tiled score / class with obj-compaction --------------
__global__ void k_score(const float* __restrict__ pred) {
    __shared__ float sp[APB * NCH];            // 87040 B
    __shared__ short wl[APB];
    __shared__ int   nvalid;
    int b  = blockIdx.y;
    int a0 = blockIdx.x * APB;
    int tid = threadIdx.x;                     // 512 threads
    int cnt = min(APB, NANCH - a0);            // 256 or 112; both %4==0
    int n4  = (cnt * NCH) >> 2;                // float4 count (divisible)

    if (tid == 0) nvalid = 0;
    const float4* src = (const float4*)(pred + ((size_t)b * NANCH + a0) * NCH);
    float4* dst = (float4*)sp;
    for (int i = tid; i < n4; i += 512) dst[i] = src[i];
    __syncthreads();

    // obj pass: invalid anchors finalized here; valid ids compacted to worklist
    for (int a = tid; a < cnt; a += 512) {
        float obj = sp[a * NCH + 4];
        if (obj > CONF_THR) {
            int pos = atomicAdd(&nvalid, 1);
            wl[pos] = (short)a;
        } else {
            int ga = b * NANCH + a0 + a;       // cls of invalid anchors is never consumed
            g_score[ga] = -1.0f;
            g_cls[ga]   = 0;
        }
    }
    __syncthreads();

    // full argmax only for valid anchors (~40%)
    int nv = nvalid;
    for (int t = tid; t < nv; t += 512) {
        int a = wl[t];
        const float* row = sp + a * NCH;
        float obj = row[4];
        float best = -2.0f; int bidx = 0;
        #pragma unroll
        for (int j = 0; j < NCLS; j++) {
            float p = __fmul_rn(obj, row[5 + j]);
            if (p > best) { best = p; bidx = j; }   // strict > = first max (jnp.argmax)
        }
        int ga = b * NANCH + a0 + a;
        g_score[ga] = (best > CONF_THR) ? best : -1.0f;   // obj>CONF_THR already holds
        g_cls[ga]   = (unsigned char)bidx;
    }
}

// ---- warp-local bitonic stages (j = j0 .. 1) on 2 register keys per lane -------
__device__ __forceinline__ void wl_stages(unsigned long long& a, unsigned long long& b,
                                          int e0, int k, int j0) {
    for (int j = j0; j >= 2; j >>= 1) {
        int jl = j >> 1;
        unsigned long long oa = __shfl_xor_sync(0xffffffffu, a, jl);
        unsigned long long ob = __shfl_xor_sync(0xffffffffu, b, jl);
        bool asc   = ((e0 & k) == 0);
        bool lower = ((e0 & j) == 0);
        bool keepmin = (lower == asc);
        a = keepmin ? (a < oa ? a : oa) : (a > oa ? a : oa);
        b = keepmin ? (b < ob ? b : ob) : (b > ob ? b : ob);
    }
    bool asc = ((e0 & k) == 0);
    if ((a > b) == asc) { unsigned long long t = a; a = b; b = t; }
}

// ---------------- K2: per-image exact top-1024 via histogram + partial bitonic --
__global__ void k_select(const float* __restrict__ pred) {
    int b   = blockIdx.x;
    int tid = threadIdx.x;                 // 1024 threads
    __shared__ int hist[NBINS];
    __shared__ unsigned long long sbuf[2 * TOPK];
    __shared__ int partial[1024];
    __shared__ int sup[32];
    __shared__ int sh_T;
    __shared__ int counter;

    for (int i = tid; i < NBINS; i += 1024) hist[i] = 0;
    if (tid == 0) counter = 0;
    __syncthreads();

    const float4* sc4 = (const float4*)(g_score + (size_t)b * NANCH);
    const int N4 = NANCH / 4;              // 6300, exact
    const float kBinScale = (float)NBINS / 0.4f;

    for (int i = tid; i < N4; i += 1024) {
        float4 v = sc4[i];
        float s0 = v.x, s1 = v.y, s2 = v.z, s3 = v.w;
        if (s0 > CONF_THR) { int bin = min(max((int)((s0 - CONF_THR) * kBinScale), 0), NBINS - 1); atomicAdd(&hist[bin], 1); }
        if (s1 > CONF_THR) { int bin = min(max((int)((s1 - CONF_THR) * kBinScale), 0), NBINS - 1); atomicAdd(&hist[bin], 1); }
        if (s2 > CONF_THR) { int bin = min(max((int)((s2 - CONF_THR) * kBinScale), 0), NBINS - 1); atomicAdd(&hist[bin], 1); }
        if (s3 > CONF_THR) { int bin = min(max((int)((s3 - CONF_THR) * kBinScale), 0), NBINS - 1); atomicAdd(&hist[bin], 1); }
    }
    __syncthreads();

    int ps = 0;
    #pragma unroll
    for (int k = 0; k < 4; k++) ps += hist[4 * tid + k];
    partial[tid] = ps;
    __syncthreads();

    if (tid < 32) {
        int s = 0;
        for (int g = 0; g < 32; g++) s += partial[32 * tid + g];
        sup[tid] = s;
        __syncwarp();
        if (tid == 0) {
            int acc = 0, T = 0, l;
            for (l = 31; l >= 0; l--) { if (acc + sup[l] >= TOPK) break; acc += sup[l]; }
            if (l >= 0) {
                int g;
                for (g = 31; g >= 0; g--) { int v = partial[32 * l + g]; if (acc + v >= TOPK) break; acc += v; }
                if (g < 0) g = 0;
                int bb;
                for (bb = 3; bb >= 0; bb--) { int v = hist[4 * (32 * l + g) + bb]; if (acc + v >= TOPK) break; acc += v; }
                if (bb < 0) bb = 0;
                T = 4 * (32 * l + g) + bb;
            }
            sh_T = T;
        }
    }
    __syncthreads();
    int T = sh_T;

    for (int i = tid; i < N4; i += 1024) {
        float4 v = sc4[i];
        #pragma unroll
        for (int u = 0; u < 4; u++) {
            float s = (u == 0) ? v.x : (u == 1) ? v.y : (u == 2) ? v.z : v.w;
            if (s > CONF_THR) {
                int bin = min(max((int)((s - CONF_THR) * kBinScale), 0), NBINS - 1);
                if (bin >= T) {
                    int pos = atomicAdd(&counter, 1);
                    if (pos < 2 * TOPK) {
                        unsigned int ub = __float_as_uint(s) ^ 0x80000000u;  // order-preserving
                        sbuf[pos] = (((unsigned long long)(~ub)) << 32) | (unsigned int)(4 * i + u);
                    }
                }
            }
        }
    }
    __syncthreads();
    int M = min(counter, 2 * TOPK);
    for (int i = tid; i < 2 * TOPK; i += 1024)
        if (i >= M) sbuf[i] = 0xFFFFFFFFFFFFFFFFull;
    __syncthreads();

    // partial bitonic: full network through k=1024, then min-merge + sort of the
    // lower 1024 only (upper half never emitted). Identical compare-network prefix.
    {
        int lane = tid & 31, wchunk = tid >> 5;
        int e0 = wchunk * 64 + 2 * lane;           // this lane's even element

        unsigned long long a = sbuf[e0], bk = sbuf[e0 + 1];
        #pragma unroll
        for (int k = 2; k <= 64; k <<= 1)
            wl_stages(a, bk, e0, k, (k >> 1) > 32 ? 32 : (k >> 1));
        sbuf[e0] = a; sbuf[e0 + 1] = bk;
        __syncthreads();

        for (int k = 128; k <= 1024; k <<= 1) {
            for (int j = k >> 1; j >= 64; j >>= 1) {
                #pragma unroll
                for (int e = tid; e < 2 * TOPK; e += 1024) {
                    int partner = e ^ j;
                    if (partner > e) {
                        bool asc = ((e & k) == 0);
                        unsigned long long x = sbuf[e], y = sbuf[partner];
                        if ((x > y) == asc) { sbuf[e] = y; sbuf[partner] = x; }
                    }
                }
                __syncthreads();
            }
            a = sbuf[e0]; bk = sbuf[e0 + 1];
            wl_stages(a, bk, e0, k, 32);
            sbuf[e0] = a; sbuf[e0 + 1] = bk;
            __syncthreads();
        }

        // k=2048 stage: j=1024 min-merge, then finish lower half only
        {
            unsigned long long x = sbuf[tid], y = sbuf[tid + TOPK];
            if (x > y) { sbuf[tid] = y; sbuf[tid + TOPK] = x; }
        }
        __syncthreads();
        for (int j = 512; j >= 64; j >>= 1) {
            int partner = tid ^ j;
            if (partner > tid) {
                unsigned long long x = sbuf[tid], y = sbuf[partner];
                if (x > y) { sbuf[tid] = y; sbuf[partner] = x; }
            }
            __syncthreads();
        }
        if (wchunk < 16) {
            a = sbuf[e0]; bk = sbuf[e0 + 1];
            wl_stages(a, bk, e0, 4096, 32);
            sbuf[e0] = a; sbuf[e0 + 1] = bk;
        }
        __syncthreads();
    }

    // emit top-1024: idx, score, class, unoffset box, class-offset nms box
    if (tid < TOPK) {
        int slot = b * TOPK + tid;
        if (tid < M) {
            unsigned long long key = sbuf[tid];
            int idx = (int)(key & 0xFFFFFFFFu);
            unsigned int u = ~((unsigned int)(key >> 32));
            float s = __uint_as_float(u ^ 0x80000000u);
            g_topk_score[slot] = s;
            g_topk_idx[slot]   = idx;
            const float* p = pred + ((size_t)b * NANCH + idx) * NCH;
            float cx = p[0], cy = p[1], w = p[2], h = p[3];
            float hw = __fmul_rn(w, 0.5f), hh = __fmul_rn(h, 0.5f);
            float x1 = __fsub_rn(cx, hw), y1 = __fsub_rn(cy, hh);
            float x2 = __fadd_rn(cx, hw), y2 = __fadd_rn(cy, hh);
            float clsf = (float)g_cls[(size_t)b * NANCH + idx];
            float off = __fmul_rn(clsf, OFFS);
            g_obox[slot] = make_float4(x1, y1, x2, y2);
            g_clsf[slot] = clsf;
            g_nmsbox[slot] = make_float4(__fadd_rn(x1, off), __fadd_rn(y1, off),
                                         __fadd_rn(x2, off), __fadd_rn(y2, off));
        } else {
            g_topk_score[slot] = -1.0f;
            g_topk_idx[slot]   = 0;
            g_obox[slot] = make_float4(0.f, 0.f, 0.f, 0.f);
            g_clsf[slot] = 0.f;
            float far = -1.0e9f - (float)tid * 16.0f;   // inert: never kept, never suppresses
            g_nmsbox[slot] = make_float4(far, far, far + 1.0f, far + 1.0f);
        }
    }
}

// ---------------- K3: suppression bitmask; div only when inter > 0 -------------
__global__ void k_mask() {
    int b = blockIdx.x, q = blockIdx.y;     // q in [0,8): column eighth (128 cols)
    int i = threadIdx.x;                    // 1024 threads, one row each
    __shared__ float4 boxes[TOPK];
    __shared__ float  areas[TOPK];
    for (int t = threadIdx.x; t < TOPK; t += 1024) {
        float4 v = g_nmsbox[b * TOPK + t];
        boxes[t] = v;
        areas[t] = __fmul_rn(__fsub_rn(v.z, v.x), __fsub_rn(v.w, v.y));
    }
    __syncthreads();

    float4 bi = boxes[i];
    float area_i = areas[i];
    int j0 = q * 128;
    #pragma unroll
    for (int w = 0; w < 4; w++) {
        unsigned int m = 0;
        #pragma unroll 4
        for (int t = 0; t < 32; t++) {
            int j = j0 + w * 32 + t;
            if (j > i) {
                float4 bj = boxes[j];
                float ltx = fmaxf(bi.x, bj.x), lty = fmaxf(bi.y, bj.y);
                float rbx = fminf(bi.z, bj.z), rby = fminf(bi.w, bj.w);
                float wx = fmaxf(__fsub_rn(rbx, ltx), 0.0f);
                float wy = fmaxf(__fsub_rn(rby, lty), 0.0f);
                float inter = __fmul_rn(wx, wy);
                if (inter > 0.0f) {         // inter==0 -> iou==+0, never > 0.45
                    float denom = __fadd_rn(__fsub_rn(__fadd_rn(area_i, areas[j]), inter), 1e-9f);
                    float iou = inter / denom;
                    if (iou > IOU_THR) m |= (1u << t);
                }
            }
        }
        g_mask[((size_t)b * TOPK + i) * 32 + q * 4 + w] = m;
    }
}

// ---------------- K4: full-mask smem + REDUX.MIN warp walk ----------------------
__global__ void k_out(const float* __restrict__ logits,
                      float* __restrict__ out) {
    extern __shared__ unsigned char dyn[];
    unsigned int* s_mask32 = (unsigned int*)dyn;                    // TOPK*32 u32 = 128 KB
    float* s_score = (float*)(dyn + TOPK * 32 * sizeof(unsigned int)); // 4 KB
    __shared__ int sel[MAXDET];
    __shared__ int sh_count;

    int b   = blockIdx.x;
    int tid = threadIdx.x;                  // 1024 threads

    float myscore = g_topk_score[b * TOPK + tid];
    s_score[tid] = myscore;

    // stage entire mask: 8192 uint4 -> 8 per thread, coalesced
    const uint4* gm = (const uint4*)(g_mask + (size_t)b * TOPK * 32);
    uint4* sm4 = (uint4*)s_mask32;
    #pragma unroll
    for (int t = 0; t < 8; t++) sm4[t * 1024 + tid] = gm[t * 1024 + tid];

    // validity is a prefix (scores sorted desc): nv = number of valid entries
    int nv = __syncthreads_count(myscore > CONF_THR);

    if (tid < 32) {
        // lane L owns removed bits for indices [32L, 32L+32)
        int lane = tid;
        int r = nv - lane * 32;
        unsigned int validw = (r >= 32) ? 0xFFFFFFFFu : ((r <= 0) ? 0u : ((1u << r) - 1u));
        unsigned int rem = 0;
        int count = 0;
        while (count < MAXDET) {
            unsigned int todo = validw & ~rem;
            unsigned int cand = todo ? ((unsigned int)(lane * 32) + __ffs(todo) - 1u)
                                     : 0xFFFFFFFFu;
            unsigned int i = __reduce_min_sync(0xffffffffu, cand);
            if (i == 0xFFFFFFFFu) break;
            if (lane == 0) sel[count] = (int)i;
            count++;
            rem |= s_mask32[(size_t)i * 32 + lane];        // parallel OR, one LDS per lane
            if ((i >> 5) == (unsigned int)lane) rem |= (1u << (i & 31u));  // consume kept bit
        }
        if (lane == 0) sh_count = count;
    }
    __syncthreads();
    int count = sh_count;

    float* det  = out;                                      // [B,300,6]
    float* vout = out + BATCH * MAXDET * 6;                 // [B,300]
    float* lout = vout + BATCH * MAXDET;                    // [B,300,80]

    for (int s = tid; s < MAXDET; s += 1024) {
        float d0 = 0, d1 = 0, d2 = 0, d3 = 0, d4 = 0, d5 = 0, v = 0;
        if (s < count) {
            int i = sel[s];
            float4 o = g_obox[b * TOPK + i];                // linear per-slot arrays only
            d0 = o.x; d1 = o.y; d2 = o.z; d3 = o.w;
            d4 = s_score[i];
            d5 = g_clsf[b * TOPK + i];
            v = 1.0f;
        }
        float* dr = det + ((size_t)b * MAXDET + s) * 6;
        dr[0] = d0; dr[1] = d1; dr[2] = d2; dr[3] = d3; dr[4] = d4; dr[5] = d5;
        vout[b * MAXDET + s] = v;
    }

    for (int e = tid; e < MAXDET * NCLS; e += 1024) {
        int s = e / NCLS, c = e % NCLS;
        float v = 0.0f;
        if (s < count) {
            int i   = sel[s];
            int idx = g_topk_idx[b * TOPK + i];
            v = logits[((size_t)b * NANCH + idx) * NCLS + c];
        }
        lout[((size_t)b * MAXDET + s) * NCLS + c] = v;
    }
}

// ---------------- launch --------------------------------------------------------
extern "C" void kernel_launch(void* const* d_in, const int* in_sizes, int n_in,
                              void* d_out, int out_size) {
    (void)in_sizes; (void)n_in; (void)out_size;
    const float* pred   = (const float*)d_in[0];
    const float* logits = (const float*)d_in[1];
    float* out = (float*)d_out;

    const int KOUT_SMEM = TOPK * 32 * (int)sizeof(unsigned int) + TOPK * (int)sizeof(float);
    cudaFuncSetAttribute(k_out, cudaFuncAttributeMaxDynamicSharedMemorySize, KOUT_SMEM);

    int nxblocks = (NANCH + APB - 1) / APB;          // 99
    k_score<<<dim3(nxblocks, BATCH), 512>>>(pred);
    k_select<<<BATCH, 1024>>>(pred);
    k_mask<<<dim3(BATCH, 8), 1024>>>();
    k_out<<<BATCH, 1024, KOUT_SMEM>>>(logits, out);
}

// round 17
// speedup vs baseline: 1.6040x; 1.1040x over previous
#include <cuda_runtime.h>
#include <cstdint>

#define BATCH   16
#define NANCH   25200
#define NCH     85
#define NCLS    80
#define TOPK    1024
#define MAXDET  300
#define CONF_THR 0.6f
#define IOU_THR  0.45f
#define OFFS     4096.0f
#define NBINS    4096
#define APB      256          // anchors per block in k_score

// ---------------- static device scratch (no allocations allowed) ----------------
__device__ float         g_score[BATCH * NANCH];
__device__ unsigned char g_cls[BATCH * NANCH];
__device__ int           g_topk_idx[BATCH * TOPK];
__device__ float         g_topk_score[BATCH * TOPK];
__device__ float         g_clsf[BATCH * TOPK];
__device__ float4        g_obox[BATCH * TOPK];
__device__ float4        g_nmsbox[BATCH * TOPK];
__device__ __align__(16) unsigned int g_mask[BATCH * TOPK * 32];

// ---------------- K1: two-phase score — obj-only pass, then warp argmax ---------
__global__ void k_score(const float* __restrict__ pred) {
    __shared__ short wl[APB];
    __shared__ float wlobj[APB];
    __shared__ int   nvalid;
    int b  = blockIdx.y;
    int a0 = blockIdx.x * APB;
    int tid = threadIdx.x;                     // 256 threads
    int cnt = min(APB, NANCH - a0);

    if (tid == 0) nvalid = 0;
    __syncthreads();

    // phase 1: read only obj; finalize invalid anchors; compact valid ids
    if (tid < cnt) {
        float obj = pred[((size_t)b * NANCH + a0 + tid) * NCH + 4];
        if (obj > CONF_THR) {
            int pos = atomicAdd(&nvalid, 1);
            wl[pos]   = (short)tid;
            wlobj[pos] = obj;
        } else {
            int ga = b * NANCH + a0 + tid;     // cls of invalid anchors never consumed
            g_score[ga] = -1.0f;
            g_cls[ga]   = 0;
        }
    }
    __syncthreads();

    // phase 2: warp per valid anchor, coalesced cls reads + shfl argmax (R1 pattern)
    int nv = nvalid;
    int wid = tid >> 5, lane = tid & 31;       // 8 warps
    for (int t = wid; t < nv; t += 8) {
        int a = wl[t];
        float obj = wlobj[t];
        const float* row = pred + ((size_t)b * NANCH + a0 + a) * NCH;
        float best = -2.0f; int bidx = 0;
        #pragma unroll
        for (int r = 0; r < 3; r++) {
            int j = lane + 32 * r;
            if (j < NCLS) {
                float p = __fmul_rn(obj, row[5 + j]);
                if (p > best) { best = p; bidx = j; }   // strict > keeps lower index
            }
        }
        #pragma unroll
        for (int off = 16; off > 0; off >>= 1) {
            float ob = __shfl_down_sync(0xffffffffu, best, off);
            int   oi = __shfl_down_sync(0xffffffffu, bidx, off);
            if (ob > best || (ob == best && oi < bidx)) { best = ob; bidx = oi; }
        }
        if (lane == 0) {
            int ga = b * NANCH + a0 + a;
            g_score[ga] = (best > CONF_THR) ? best : -1.0f;  // obj>CONF_THR already holds
            g_cls[ga]   = (unsigned char)bidx;
        }
    }
}

// ---- warp-local bitonic stages (j = j0 .. 1) on 2 register keys per lane -------
__device__ __forceinline__ void wl_stages(unsigned long long& a, unsigned long long& b,
                                          int e0, int k, int j0) {
    for (int j = j0; j >= 2; j >>= 1) {
        int jl = j >> 1;
        unsigned long long oa = __shfl_xor_sync(0xffffffffu, a, jl);
        unsigned long long ob = __shfl_xor_sync(0xffffffffu, b, jl);
        bool asc   = ((e0 & k) == 0);
        bool lower = ((e0 & j) == 0);
        bool keepmin = (lower == asc);
        a = keepmin ? (a < oa ? a : oa) : (a > oa ? a : oa);
        b = keepmin ? (b < ob ? b : ob) : (b > ob ? b : ob);
    }
    bool asc = ((e0 & k) == 0);
    if ((a > b) == asc) { unsigned long long t = a; a = b; b = t; }
}

// ---------------- K2: per-image exact top-1024 via histogram + partial bitonic --
__global__ void k_select(const float* __restrict__ pred) {
    int b   = blockIdx.x;
    int tid = threadIdx.x;                 // 1024 threads
    __shared__ int hist[NBINS];
    __shared__ unsigned long long sbuf[2 * TOPK];
    __shared__ int partial[1024];
    __shared__ int sup[32];
    __shared__ int sh_T;
    __shared__ int counter;

    for (int i = tid; i < NBINS; i += 1024) hist[i] = 0;
    if (tid == 0) counter = 0;
    __syncthreads();

    const float4* sc4 = (const float4*)(g_score + (size_t)b * NANCH);
    const int N4 = NANCH / 4;              // 6300, exact
    const float kBinScale = (float)NBINS / 0.4f;

    for (int i = tid; i < N4; i += 1024) {
        float4 v = sc4[i];
        float s0 = v.x, s1 = v.y, s2 = v.z, s3 = v.w;
        if (s0 > CONF_THR) { int bin = min(max((int)((s0 - CONF_THR) * kBinScale), 0), NBINS - 1); atomicAdd(&hist[bin], 1); }
        if (s1 > CONF_THR) { int bin = min(max((int)((s1 - CONF_THR) * kBinScale), 0), NBINS - 1); atomicAdd(&hist[bin], 1); }
        if (s2 > CONF_THR) { int bin = min(max((int)((s2 - CONF_THR) * kBinScale), 0), NBINS - 1); atomicAdd(&hist[bin], 1); }
        if (s3 > CONF_THR) { int bin = min(max((int)((s3 - CONF_THR) * kBinScale), 0), NBINS - 1); atomicAdd(&hist[bin], 1); }
    }
    __syncthreads();

    int ps = 0;
    #pragma unroll
    for (int k = 0; k < 4; k++) ps += hist[4 * tid + k];
    partial[tid] = ps;
    __syncthreads();

    if (tid < 32) {
        int s = 0;
        for (int g = 0; g < 32; g++) s += partial[32 * tid + g];
        sup[tid] = s;
        __syncwarp();
        if (tid == 0) {
            int acc = 0, T = 0, l;
            for (l = 31; l >= 0; l--) { if (acc + sup[l] >= TOPK) break; acc += sup[l]; }
            if (l >= 0) {
                int g;
                for (g = 31; g >= 0; g--) { int v = partial[32 * l + g]; if (acc + v >= TOPK) break; acc += v; }
                if (g < 0) g = 0;
                int bb;
                for (bb = 3; bb >= 0; bb--) { int v = hist[4 * (32 * l + g) + bb]; if (acc + v >= TOPK) break; acc += v; }
                if (bb < 0) bb = 0;
                T = 4 * (32 * l + g) + bb;
            }
            sh_T = T;
        }
    }
    __syncthreads();
    int T = sh_T;

    for (int i = tid; i < N4; i += 1024) {
        float4 v = sc4[i];
        #pragma unroll
        for (int u = 0; u < 4; u++) {
            float s = (u == 0) ? v.x : (u == 1) ? v.y : (u == 2) ? v.z : v.w;
            if (s > CONF_THR) {
                int bin = min(max((int)((s - CONF_THR) * kBinScale), 0), NBINS - 1);
                if (bin >= T) {
                    int pos = atomicAdd(&counter, 1);
                    if (pos < 2 * TOPK) {
                        unsigned int ub = __float_as_uint(s) ^ 0x80000000u;  // order-preserving
                        sbuf[pos] = (((unsigned long long)(~ub)) << 32) | (unsigned int)(4 * i + u);
                    }
                }
            }
        }
    }
    __syncthreads();
    int M = min(counter, 2 * TOPK);
    for (int i = tid; i < 2 * TOPK; i += 1024)
        if (i >= M) sbuf[i] = 0xFFFFFFFFFFFFFFFFull;
    __syncthreads();

    // partial bitonic: full network through k=1024, then min-merge + sort of the
    // lower 1024 only (upper half never emitted). Identical compare-network prefix.
    {
        int lane = tid & 31, wchunk = tid >> 5;
        int e0 = wchunk * 64 + 2 * lane;           // this lane's even element

        unsigned long long a = sbuf[e0], bk = sbuf[e0 + 1];
        #pragma unroll
        for (int k = 2; k <= 64; k <<= 1)
            wl_stages(a, bk, e0, k, (k >> 1) > 32 ? 32 : (k >> 1));
        sbuf[e0] = a; sbuf[e0 + 1] = bk;
        __syncthreads();

        for (int k = 128; k <= 1024; k <<= 1) {
            for (int j = k >> 1; j >= 64; j >>= 1) {
                #pragma unroll
                for (int e = tid; e < 2 * TOPK; e += 1024) {
                    int partner = e ^ j;
                    if (partner > e) {
                        bool asc = ((e & k) == 0);
                        unsigned long long x = sbuf[e], y = sbuf[partner];
                        if ((x > y) == asc) { sbuf[e] = y; sbuf[partner] = x; }
                    }
                }
                __syncthreads();
            }
            a = sbuf[e0]; bk = sbuf[e0 + 1];
            wl_stages(a, bk, e0, k, 32);
            sbuf[e0] = a; sbuf[e0 + 1] = bk;
            __syncthreads();
        }

        // k=2048 stage: j=1024 min-merge, then finish lower half only
        {
            unsigned long long x = sbuf[tid], y = sbuf[tid + TOPK];
            if (x > y) { sbuf[tid] = y; sbuf[tid + TOPK] = x; }
        }
        __syncthreads();
        for (int j = 512; j >= 64; j >>= 1) {
            int partner = tid ^ j;
            if (partner > tid) {
                unsigned long long x = sbuf[tid], y = sbuf[partner];
                if (x > y) { sbuf[tid] = y; sbuf[partner] = x; }
            }
            __syncthreads();
        }
        if (wchunk < 16) {
            a = sbuf[e0]; bk = sbuf[e0 + 1];
            wl_stages(a, bk, e0, 4096, 32);
            sbuf[e0] = a; sbuf[e0 + 1] = bk;
        }
        __syncthreads();
    }

    // emit top-1024: idx, score, class, unoffset box, class-offset nms box
    if (tid < TOPK) {
        int slot = b * TOPK + tid;
        if (tid < M) {
            unsigned long long key = sbuf[tid];
            int idx = (int)(key & 0xFFFFFFFFu);
            unsigned int u = ~((unsigned int)(key >> 32));
            float s = __uint_as_float(u ^ 0x80000000u);
            g_topk_score[slot] = s;
            g_topk_idx[slot]   = idx;
            const float* p = pred + ((size_t)b * NANCH + idx) * NCH;
            float cx = p[0], cy = p[1], w = p[2], h = p[3];
            float hw = __fmul_rn(w, 0.5f), hh = __fmul_rn(h, 0.5f);
            float x1 = __fsub_rn(cx, hw), y1 = __fsub_rn(cy, hh);
            float x2 = __fadd_rn(cx, hw), y2 = __fadd_rn(cy, hh);
            float clsf = (float)g_cls[(size_t)b * NANCH + idx];
            float off = __fmul_rn(clsf, OFFS);
            g_obox[slot] = make_float4(x1, y1, x2, y2);
            g_clsf[slot] = clsf;
            g_nmsbox[slot] = make_float4(__fadd_rn(x1, off), __fadd_rn(y1, off),
                                         __fadd_rn(x2, off), __fadd_rn(y2, off));
        } else {
            g_topk_score[slot] = -1.0f;
            g_topk_idx[slot]   = 0;
            g_obox[slot] = make_float4(0.f, 0.f, 0.f, 0.f);
            g_clsf[slot] = 0.f;
            float far = -1.0e9f - (float)tid * 16.0f;   // inert: never kept, never suppresses
            g_nmsbox[slot] = make_float4(far, far, far + 1.0f, far + 1.0f);
        }
    }
}

// ---------------- K3: suppression bitmask; div only when inter > 0 -------------
__global__ void k_mask() {
    int b = blockIdx.x, q = blockIdx.y;     // q in [0,8): column eighth (128 cols)
    int i = threadIdx.x;                    // 1024 threads, one row each
    __shared__ float4 boxes[TOPK];
    __shared__ float  areas[TOPK];
    for (int t = threadIdx.x; t < TOPK; t += 1024) {
        float4 v = g_nmsbox[b * TOPK + t];
        boxes[t] = v;
        areas[t] = __fmul_rn(__fsub_rn(v.z, v.x), __fsub_rn(v.w, v.y));
    }
    __syncthreads();

    float4 bi = boxes[i];
    float area_i = areas[i];
    int j0 = q * 128;
    #pragma unroll
    for (int w = 0; w < 4; w++) {
        unsigned int m = 0;
        #pragma unroll 4
        for (int t = 0; t < 32; t++) {
            int j = j0 + w * 32 + t;
            if (j > i) {
                float4 bj = boxes[j];
                float ltx = fmaxf(bi.x, bj.x), lty = fmaxf(bi.y, bj.y);
                float rbx = fminf(bi.z, bj.z), rby = fminf(bi.w, bj.w);
                float wx = fmaxf(__fsub_rn(rbx, ltx), 0.0f);
                float wy = fmaxf(__fsub_rn(rby, lty), 0.0f);
                float inter = __fmul_rn(wx, wy);
                if (inter > 0.0f) {         // inter==0 -> iou==+0, never > 0.45
                    float denom = __fadd_rn(__fsub_rn(__fadd_rn(area_i, areas[j]), inter), 1e-9f);
                    float iou = inter / denom;
                    if (iou > IOU_THR) m |= (1u << t);
                }
            }
        }
        g_mask[((size_t)b * TOPK + i) * 32 + q * 4 + w] = m;
    }
}

// ---------------- K4: full-mask smem + REDUX.MIN warp walk ----------------------
__global__ void k_out(const float* __restrict__ logits,
                      float* __restrict__ out) {
    extern __shared__ unsigned char dyn[];
    unsigned int* s_mask32 = (unsigned int*)dyn;                    // TOPK*32 u32 = 128 KB
    float* s_score = (float*)(dyn + TOPK * 32 * sizeof(unsigned int)); // 4 KB
    __shared__ int sel[MAXDET];
    __shared__ int sh_count;

    int b   = blockIdx.x;
    int tid = threadIdx.x;                  // 1024 threads

    float myscore = g_topk_score[b * TOPK + tid];
    s_score[tid] = myscore;

    // stage entire mask: 8192 uint4 -> 8 per thread, coalesced
    const uint4* gm = (const uint4*)(g_mask + (size_t)b * TOPK * 32);
    uint4* sm4 = (uint4*)s_mask32;
    #pragma unroll
    for (int t = 0; t < 8; t++) sm4[t * 1024 + tid] = gm[t * 1024 + tid];

    // validity is a prefix (scores sorted desc): nv = number of valid entries
    int nv = __syncthreads_count(myscore > CONF_THR);

    if (tid < 32) {
        // lane L owns removed bits for indices [32L, 32L+32)
        int lane = tid;
        int r = nv - lane * 32;
        unsigned int validw = (r >= 32) ? 0xFFFFFFFFu : ((r <= 0) ? 0u : ((1u << r) - 1u));
        unsigned int rem = 0;
        int count = 0;
        while (count < MAXDET) {
            unsigned int todo = validw & ~rem;
            unsigned int cand = todo ? ((unsigned int)(lane * 32) + __ffs(todo) - 1u)
                                     : 0xFFFFFFFFu;
            unsigned int i = __reduce_min_sync(0xffffffffu, cand);
            if (i == 0xFFFFFFFFu) break;
            if (lane == 0) sel[count] = (int)i;
            count++;
            rem |= s_mask32[(size_t)i * 32 + lane];        // parallel OR, one LDS per lane
            if ((i >> 5) == (unsigned int)lane) rem |= (1u << (i & 31u));  // consume kept bit
        }
        if (lane == 0) sh_count = count;
    }
    __syncthreads();
    int count = sh_count;

    float* det  = out;                                      // [B,300,6]
    float* vout = out + BATCH * MAXDET * 6;                 // [B,300]
    float* lout = vout + BATCH * MAXDET;                    // [B,300,80]

    for (int s = tid; s < MAXDET; s += 1024) {
        float d0 = 0, d1 = 0, d2 = 0, d3 = 0, d4 = 0, d5 = 0, v = 0;
        if (s < count) {
            int i = sel[s];
            float4 o = g_obox[b * TOPK + i];                // linear per-slot arrays only
            d0 = o.x; d1 = o.y; d2 = o.z; d3 = o.w;
            d4 = s_score[i];
            d5 = g_clsf[b * TOPK + i];
            v = 1.0f;
        }
        float* dr = det + ((size_t)b * MAXDET + s) * 6;
        dr[0] = d0; dr[1] = d1; dr[2] = d2; dr[3] = d3; dr[4] = d4; dr[5] = d5;
        vout[b * MAXDET + s] = v;
    }

    for (int e = tid; e < MAXDET * NCLS; e += 1024) {
        int s = e / NCLS, c = e % NCLS;
        float v = 0.0f;
        if (s < count) {
            int i   = sel[s];
            int idx = g_topk_idx[b * TOPK + i];
            v = logits[((size_t)b * NANCH + idx) * NCLS + c];
        }
        lout[((size_t)b * MAXDET + s) * NCLS + c] = v;
    }
}

// ---------------- launch --------------------------------------------------------
extern "C" void kernel_launch(void* const* d_in, const int* in_sizes, int n_in,
                              void* d_out, int out_size) {
    (void)in_sizes; (void)n_in; (void)out_size;
    const float* pred   = (const float*)d_in[0];
    const float* logits = (const float*)d_in[1];
    float* out = (float*)d_out;

    const int KOUT_SMEM = TOPK * 32 * (int)sizeof(unsigned int) + TOPK * (int)sizeof(float);
    cudaFuncSetAttribute(k_out, cudaFuncAttributeMaxDynamicSharedMemorySize, KOUT_SMEM);

    int nxblocks = (NANCH + APB - 1) / APB;          // 99
    k_score<<<dim3(nxblocks, BATCH), 256>>>(pred);
    k_select<<<BATCH, 1024>>>(pred);
    k_mask<<<dim3(BATCH, 8), 1024>>>();
    k_out<<<BATCH, 1024, KOUT_SMEM>>>(logits, out);
}